// round 8
// baseline (speedup 1.0000x reference)
#include <cuda_runtime.h>
#include <cuda_fp16.h>
#include <cstdint>

// final = rmsnorm( x @ (0.125 * w_out @ w_v)^T + b_out ) * g * 32
// R8: conv_w (tiny) -> fused {prep HMMA GEMM on 64 SMs || x->fp16 on 84 SMs}
//     -> main GEMM BM=256 x BN=128 (512 thr) fp16 HMMA -> row L2 norm.

constexpr int DIM    = 1024;
constexpr int HIDDEN = 512;
constexpr int BATCH  = 16384;

constexpr int BM = 256;                         // batch rows per CTA
constexpr int BN = 128;                         // dim cols per CTA
constexpr int BK = 64;
constexpr int KCHUNKS  = DIM / BK;              // 16
constexpr int KCHUNKSP = HIDDEN / BK;           // 8
constexpr int NSTAGE = 3;

constexpr uint32_t PITCH = 144;
constexpr uint32_t SA = 0;                      // X tile: 256 rows
constexpr uint32_t SB = 256 * PITCH;            // W tile: 128 rows
constexpr uint32_t STAGE = 384 * PITCH;         // 55296
constexpr uint32_t GEMM_SMEM = NSTAGE * STAGE;  // 165888

constexpr uint32_t PA_HI = 0;
constexpr uint32_t PA_LO = 128 * PITCH;
constexpr uint32_t PB_HI = 2 * 128 * PITCH;
constexpr uint32_t PB_LO = 3 * 128 * PITCH;
constexpr uint32_t STAGE_P = 4 * 128 * PITCH;   // 73728
constexpr uint32_t PREP_SMEM = 2 * STAGE_P;     // 147456

// Static device scratch (allocation-free rule).
__device__ __half g_Xh[BATCH * DIM];
__device__ __half g_Wh[DIM * DIM];
__device__ __half g_WOhi[DIM * HIDDEN];
__device__ __half g_WOlo[DIM * HIDDEN];
__device__ __half g_WvThi[DIM * HIDDEN];
__device__ __half g_WvTlo[DIM * HIDDEN];

// ---------------------------------------------------------------------------
__device__ __forceinline__ uint32_t smem_u32(const void* p) {
    uint32_t a;
    asm("{ .reg .u64 t; cvta.to.shared.u64 t, %1; cvt.u32.u64 %0, t; }"
        : "=r"(a) : "l"(p));
    return a;
}
__device__ __forceinline__ void cp16(uint32_t dst, const void* src) {
    asm volatile("cp.async.cg.shared.global [%0], [%1], 16;"
                 :: "r"(dst), "l"(src) : "memory");
}
#define CP_COMMIT() asm volatile("cp.async.commit_group;" ::: "memory")
#define CP_WAIT(n)  asm volatile("cp.async.wait_group %0;" :: "n"(n) : "memory")

#define LDSM4(r, addr)                                                         \
    asm volatile("ldmatrix.sync.aligned.m8n8.x4.shared.b16 "                   \
                 "{%0, %1, %2, %3}, [%4];"                                     \
                 : "=r"((r)[0]), "=r"((r)[1]), "=r"((r)[2]), "=r"((r)[3])      \
                 : "r"(addr))

#define MMA16816(c, a, b)                                                      \
    asm volatile("mma.sync.aligned.m16n8k16.row.col.f32.f16.f16.f32 "          \
                 "{%0, %1, %2, %3}, {%4, %5, %6, %7}, {%8, %9}, "              \
                 "{%0, %1, %2, %3};"                                           \
                 : "+f"((c)[0]), "+f"((c)[1]), "+f"((c)[2]), "+f"((c)[3])      \
                 : "r"((a)[0]), "r"((a)[1]), "r"((a)[2]), "r"((a)[3]),         \
                   "r"((b)[0]), "r"((b)[1]))

// ---------------------------------------------------------------------------
// conv_w: w_out -> fp16 hi/lo [n][c];  w_v -> transposed fp16 hi/lo [k][c]
// ---------------------------------------------------------------------------
__global__ __launch_bounds__(256) void conv_w_kernel(
    const float* __restrict__ w_qkv, const float* __restrict__ w_out)
{
    const int tid = threadIdx.x;
    const int b = blockIdx.x;

    if (b < 128) {
        const float4* __restrict__ w4 = reinterpret_cast<const float4*>(w_out);
        int i = b * 256 + tid;
        #pragma unroll
        for (int it = 0; it < 4; it++, i += 32768) {
            float4 v = w4[i];
            __half h0 = __float2half_rn(v.x), h1 = __float2half_rn(v.y);
            __half h2 = __float2half_rn(v.z), h3 = __float2half_rn(v.w);
            __half2* ho = reinterpret_cast<__half2*>(g_WOhi);
            __half2* lo = reinterpret_cast<__half2*>(g_WOlo);
            ho[i * 2 + 0] = __half2(h0, h1);
            ho[i * 2 + 1] = __half2(h2, h3);
            lo[i * 2 + 0] = __half2(__float2half_rn(v.x - __half2float(h0)),
                                    __float2half_rn(v.y - __half2float(h1)));
            lo[i * 2 + 1] = __half2(__float2half_rn(v.z - __half2float(h2)),
                                    __float2half_rn(v.w - __half2float(h3)));
        }
        return;
    }

    // w_v transpose: w_v[c][k] (rows [1024,1536) of w_qkv) -> WvT[k][c]
    __shared__ float tile[32][33];
    const int bb = b - 128;                  // 0..511
    const int k0 = (bb & 31) * 32;
    const int c0 = (bb >> 5) * 32;
    const int tx = tid & 31, ty = tid >> 5;
    const float* __restrict__ wv = w_qkv + (size_t)2 * HIDDEN * DIM;

    #pragma unroll
    for (int j = 0; j < 4; j++)
        tile[ty + j * 8][tx] = wv[(size_t)(c0 + ty + j * 8) * DIM + k0 + tx];
    __syncthreads();
    #pragma unroll
    for (int j = 0; j < 4; j++) {
        int k = k0 + ty + j * 8;
        float v = tile[tx][ty + j * 8];
        __half h = __float2half_rn(v);
        g_WvThi[(size_t)k * HIDDEN + c0 + tx] = h;
        g_WvTlo[(size_t)k * HIDDEN + c0 + tx] =
            __float2half_rn(v - __half2float(h));
    }
}

// ---------------------------------------------------------------------------
// Fused: blocks [0,64) = prep GEMM (3-pass fp16 split HMMA);
//        blocks [64,148) = x -> fp16 grid-stride (idle SMs).
// All blocks get PREP_SMEM dynamic smem -> 1 block/SM, exactly 148 blocks.
// ---------------------------------------------------------------------------
__device__ __forceinline__ void load_stage_p(uint32_t sb, int s, int m0b,
                                             int n0b, int kc, int tid)
{
    const uint32_t st = sb + (uint32_t)s * STAGE_P;
    const char* ah = reinterpret_cast<const char*>(g_WOhi);
    const char* al = reinterpret_cast<const char*>(g_WOlo);
    const char* bh = reinterpret_cast<const char*>(g_WvThi);
    const char* bl = reinterpret_cast<const char*>(g_WvTlo);
    const size_t kb = (size_t)kc * 128;

    #pragma unroll
    for (int j = 0; j < 4; j++) {
        int i = tid + j * 256;
        int r = i >> 3, c = i & 7;
        uint32_t so = (uint32_t)r * PITCH + c * 16;
        size_t ga = (size_t)(m0b + r) * 1024 + kb + c * 16;
        size_t gb = (size_t)(n0b + r) * 1024 + kb + c * 16;
        cp16(st + PA_HI + so, ah + ga);
        cp16(st + PA_LO + so, al + ga);
        cp16(st + PB_HI + so, bh + gb);
        cp16(st + PB_LO + so, bl + gb);
    }
}

__global__ __launch_bounds__(256) void prep_fused_kernel(
    const float4* __restrict__ x4)
{
    const int tid = threadIdx.x;

    if (blockIdx.x >= 64) {
        // ---- x conversion on the 84 SMs the prep GEMM doesn't use ----
        __half2* __restrict__ xo = reinterpret_cast<__half2*>(g_Xh);
        const int total = BATCH * DIM / 4;            // 4,194,304 float4
        const int stride = 84 * 256;
        for (int i = (blockIdx.x - 64) * 256 + tid; i < total; i += stride) {
            float4 v = x4[i];
            xo[i * 2 + 0] = __floats2half2_rn(v.x, v.y);
            xo[i * 2 + 1] = __floats2half2_rn(v.z, v.w);
        }
        return;
    }

    // ---- prep GEMM: W[n][k] = sum_c w_out[n][c] * w_vT[k][c] ----
    extern __shared__ char smem[];
    const uint32_t sb = smem_u32(smem);
    const int lane = tid & 31, wid = tid >> 5;
    const int wm = wid & 1, wn = wid >> 1;
    const int m0b = (blockIdx.x >> 3) * 128;   // n-dim of W
    const int n0b = (blockIdx.x & 7) * 128;    // k-dim of W

    float c[4][4][4] = {};

    const int rowA = lane & 15;
    const int colA = (lane >> 4) * 8;
    const int rowB = (lane & 7) + ((lane >> 4) << 3);
    const int colB = ((lane >> 3) & 1) * 8;
    const uint32_t pA = (uint32_t)(wm * 64 + rowA) * PITCH + colA * 2;
    const uint32_t pB = (uint32_t)(wn * 32 + rowB) * PITCH + colB * 2;

    load_stage_p(sb, 0, m0b, n0b, 0, tid);
    CP_COMMIT();

    for (int kc = 0; kc < KCHUNKSP; kc++) {
        const int s = kc & 1;
        if (kc + 1 < KCHUNKSP) {
            load_stage_p(sb, s ^ 1, m0b, n0b, kc + 1, tid);
            CP_COMMIT();
            CP_WAIT(1);
        } else {
            CP_WAIT(0);
        }
        __syncthreads();

        const uint32_t st = sb + (uint32_t)s * STAGE_P;
        #pragma unroll
        for (int ks = 0; ks < 4; ks++) {
            uint32_t ah[4][4], al[4][4];
            #pragma unroll
            for (int mi = 0; mi < 4; mi++) {
                uint32_t adr = st + PA_HI + pA + mi * (16 * PITCH) + ks * 32;
                LDSM4(ah[mi], adr);
                LDSM4(al[mi], adr + (PA_LO - PA_HI));
            }
            uint32_t bh[4][2], bl[4][2];
            #pragma unroll
            for (int np = 0; np < 2; np++) {
                uint32_t adr = st + PB_HI + pB + np * (16 * PITCH) + ks * 32;
                uint32_t r[4];
                LDSM4(r, adr);
                bh[np * 2][0] = r[0]; bh[np * 2][1] = r[1];
                bh[np * 2 + 1][0] = r[2]; bh[np * 2 + 1][1] = r[3];
                LDSM4(r, adr + (PB_LO - PB_HI));
                bl[np * 2][0] = r[0]; bl[np * 2][1] = r[1];
                bl[np * 2 + 1][0] = r[2]; bl[np * 2 + 1][1] = r[3];
            }
            #pragma unroll
            for (int mi = 0; mi < 4; mi++)
                #pragma unroll
                for (int ni = 0; ni < 4; ni++) {
                    MMA16816(c[mi][ni], ah[mi], bh[ni]);
                    MMA16816(c[mi][ni], ah[mi], bl[ni]);
                    MMA16816(c[mi][ni], al[mi], bh[ni]);
                }
        }
        __syncthreads();
    }

    const int mbase = m0b + wm * 64 + (lane >> 2);
    const int nbase = n0b + wn * 32 + (lane & 3) * 2;
    #pragma unroll
    for (int ni = 0; ni < 4; ni++) {
        const int n = nbase + ni * 8;
        #pragma unroll
        for (int mi = 0; mi < 4; mi++) {
            const int m = mbase + mi * 16;
            *reinterpret_cast<__half2*>(&g_Wh[(size_t)m * DIM + n]) =
                __floats2half2_rn(c[mi][ni][0], c[mi][ni][1]);
            *reinterpret_cast<__half2*>(&g_Wh[(size_t)(m + 8) * DIM + n]) =
                __floats2half2_rn(c[mi][ni][2], c[mi][ni][3]);
        }
    }
}

// ---------------------------------------------------------------------------
// Main GEMM: out[b][n] = 0.125 * sum_k X[b][k] * W[n][k] + b_out[n]
// BM=256 x BN=128, 512 threads, 4x4 warp grid, 3-stage cp.async.
// ---------------------------------------------------------------------------
__device__ __forceinline__ void load_stage(uint32_t sb, int s, int m0b, int n0b,
                                           int kc, int tid)
{
    const uint32_t st = sb + (uint32_t)s * STAGE;
    const char* xh = reinterpret_cast<const char*>(g_Xh);
    const char* wh = reinterpret_cast<const char*>(g_Wh);
    const size_t kb = (size_t)kc * 128;

    #pragma unroll
    for (int j = 0; j < 4; j++) {                 // X: 256 rows x 8 cols
        int i = tid + j * 512;
        int r = i >> 3, c = i & 7;
        cp16(st + SA + (uint32_t)r * PITCH + c * 16,
             xh + (size_t)(m0b + r) * 2048 + kb + c * 16);
    }
    #pragma unroll
    for (int j = 0; j < 2; j++) {                 // W: 128 rows x 8 cols
        int i = tid + j * 512;
        int r = i >> 3, c = i & 7;
        cp16(st + SB + (uint32_t)r * PITCH + c * 16,
             wh + (size_t)(n0b + r) * 2048 + kb + c * 16);
    }
}

__global__ __launch_bounds__(512, 1) void gemm_mma_kernel(
    const float* __restrict__ b_out, float* __restrict__ out)
{
    extern __shared__ char smem[];
    const uint32_t sb = smem_u32(smem);
    const int tid = threadIdx.x;
    const int lane = tid & 31, wid = tid >> 5;
    const int wm = wid & 3, wn = wid >> 2;        // 4 x 4 warp grid
    const int m0b = blockIdx.y * BM;
    const int n0b = blockIdx.x * BN;

    float c[4][4][4] = {};

    const int rowA = lane & 15;
    const int colA = (lane >> 4) * 8;
    const int rowB = (lane & 7) + ((lane >> 4) << 3);
    const int colB = ((lane >> 3) & 1) * 8;
    const uint32_t pA = (uint32_t)(wm * 64 + rowA) * PITCH + colA * 2;
    const uint32_t pB = (uint32_t)(wn * 32 + rowB) * PITCH + colB * 2;

    load_stage(sb, 0, m0b, n0b, 0, tid);
    CP_COMMIT();
    load_stage(sb, 1, m0b, n0b, 1, tid);
    CP_COMMIT();

    int sc = 0;
    for (int kc = 0; kc < KCHUNKS; kc++) {
        CP_WAIT(1);
        __syncthreads();

        if (kc + 2 < KCHUNKS) {
            int sp = sc + 2; if (sp >= NSTAGE) sp -= NSTAGE;
            load_stage(sb, sp, m0b, n0b, kc + 2, tid);
        }
        CP_COMMIT();

        const uint32_t st = sb + (uint32_t)sc * STAGE;
        #pragma unroll
        for (int ks = 0; ks < 4; ks++) {
            uint32_t a[4][4];
            #pragma unroll
            for (int mi = 0; mi < 4; mi++)
                LDSM4(a[mi], st + SA + pA + mi * (16 * PITCH) + ks * 32);
            uint32_t b[4][2];
            #pragma unroll
            for (int np = 0; np < 2; np++) {
                uint32_t r[4];
                LDSM4(r, st + SB + pB + np * (16 * PITCH) + ks * 32);
                b[np * 2][0] = r[0]; b[np * 2][1] = r[1];
                b[np * 2 + 1][0] = r[2]; b[np * 2 + 1][1] = r[3];
            }
            #pragma unroll
            for (int mi = 0; mi < 4; mi++)
                #pragma unroll
                for (int ni = 0; ni < 4; ni++)
                    MMA16816(c[mi][ni], a[mi], b[ni]);
        }
        if (++sc >= NSTAGE) sc -= NSTAGE;
    }

    const int mbase = m0b + wm * 64 + (lane >> 2);
    const int nbase = n0b + wn * 32 + (lane & 3) * 2;
    #pragma unroll
    for (int ni = 0; ni < 4; ni++) {
        const int n = nbase + ni * 8;
        const float2 bias = *reinterpret_cast<const float2*>(&b_out[n]);
        #pragma unroll
        for (int mi = 0; mi < 4; mi++) {
            const int m = mbase + mi * 16;
            float2 v0 = { fmaf(0.125f, c[mi][ni][0], bias.x),
                          fmaf(0.125f, c[mi][ni][1], bias.y) };
            float2 v1 = { fmaf(0.125f, c[mi][ni][2], bias.x),
                          fmaf(0.125f, c[mi][ni][3], bias.y) };
            *reinterpret_cast<float2*>(&out[(size_t)m * DIM + n]) = v0;
            *reinterpret_cast<float2*>(&out[(size_t)(m + 8) * DIM + n]) = v1;
        }
    }
}

// ---------------------------------------------------------------------------
// Row L2-normalize: out = y * (32/max(||y||,eps)) * g
// ---------------------------------------------------------------------------
__global__ __launch_bounds__(256) void rmsnorm_kernel(
    const float* __restrict__ g, float* __restrict__ y)
{
    const int warp = (blockIdx.x * blockDim.x + threadIdx.x) >> 5;
    const int lane = threadIdx.x & 31;
    if (warp >= BATCH) return;
    float* __restrict__ row = y + (size_t)warp * DIM;

    float4 vals[8];
    float ss = 0.f;
    #pragma unroll
    for (int i = 0; i < 8; i++) {
        vals[i] = *reinterpret_cast<const float4*>(&row[lane * 4 + i * 128]);
        ss += vals[i].x * vals[i].x + vals[i].y * vals[i].y +
              vals[i].z * vals[i].z + vals[i].w * vals[i].w;
    }
    #pragma unroll
    for (int o = 16; o > 0; o >>= 1) ss += __shfl_xor_sync(0xFFFFFFFFu, ss, o);
    const float inv = 32.0f / fmaxf(sqrtf(ss), 1e-12f);
    #pragma unroll
    for (int i = 0; i < 8; i++) {
        int n = lane * 4 + i * 128;
        float4 gv = *reinterpret_cast<const float4*>(&g[n]);
        float4 o;
        o.x = vals[i].x * inv * gv.x;
        o.y = vals[i].y * inv * gv.y;
        o.z = vals[i].z * inv * gv.z;
        o.w = vals[i].w * inv * gv.w;
        *reinterpret_cast<float4*>(&row[n]) = o;
    }
}

// ---------------------------------------------------------------------------
extern "C" void kernel_launch(void* const* d_in, const int* in_sizes, int n_in,
                              void* d_out, int out_size)
{
    const float* x     = (const float*)d_in[0];
    const float* w_qkv = (const float*)d_in[1];
    const float* w_out = (const float*)d_in[2];
    const float* b_out = (const float*)d_in[3];
    const float* g     = (const float*)d_in[4];
    float* out = (float*)d_out;

    cudaFuncSetAttribute(gemm_mma_kernel,
                         cudaFuncAttributeMaxDynamicSharedMemorySize, GEMM_SMEM);
    cudaFuncSetAttribute(prep_fused_kernel,
                         cudaFuncAttributeMaxDynamicSharedMemorySize, PREP_SMEM);

    conv_w_kernel<<<640, 256>>>(w_qkv, w_out);
    prep_fused_kernel<<<148, 256, PREP_SMEM>>>((const float4*)x);
    gemm_mma_kernel<<<dim3(DIM / BN, BATCH / BM), 512, GEMM_SMEM>>>(b_out, out);
    rmsnorm_kernel<<<(BATCH * 32) / 256, 256>>>(g, out);
}

// round 9
// speedup vs baseline: 1.1414x; 1.1414x over previous
#include <cuda_runtime.h>
#include <cuda_fp16.h>
#include <cstdint>

// final = rmsnorm( x @ (0.125 * w_out @ w_v)^T + b_out ) * g * 32
// R9: conv_w (tiny) -> fused {prep HMMA GEMM on 64 SMs || x->fp16 on 84 SMs}
//     -> main GEMM reverted to R7 shape (BM=128,BN=128,256thr,2 CTA/SM)
//     -> row L2 norm.

constexpr int DIM    = 1024;
constexpr int HIDDEN = 512;
constexpr int BATCH  = 16384;

constexpr int BM = 128;
constexpr int BN = 128;
constexpr int BK = 64;
constexpr int KCHUNKS  = DIM / BK;              // 16
constexpr int KCHUNKSP = HIDDEN / BK;           // 8
constexpr int NSTAGE = 3;

constexpr uint32_t PITCH = 144;
constexpr uint32_t SA = 0;
constexpr uint32_t SB = 128 * PITCH;
constexpr uint32_t STAGE = 2 * 128 * PITCH;     // 36864
constexpr uint32_t GEMM_SMEM = NSTAGE * STAGE;  // 110592

constexpr uint32_t PA_HI = 0;
constexpr uint32_t PA_LO = 128 * PITCH;
constexpr uint32_t PB_HI = 2 * 128 * PITCH;
constexpr uint32_t PB_LO = 3 * 128 * PITCH;
constexpr uint32_t STAGE_P = 4 * 128 * PITCH;   // 73728
constexpr uint32_t PREP_SMEM = 2 * STAGE_P;     // 147456

// Static device scratch (allocation-free rule).
__device__ __half g_Xh[BATCH * DIM];
__device__ __half g_Wh[DIM * DIM];
__device__ __half g_WOhi[DIM * HIDDEN];
__device__ __half g_WOlo[DIM * HIDDEN];
__device__ __half g_WvThi[DIM * HIDDEN];
__device__ __half g_WvTlo[DIM * HIDDEN];

// ---------------------------------------------------------------------------
__device__ __forceinline__ uint32_t smem_u32(const void* p) {
    uint32_t a;
    asm("{ .reg .u64 t; cvta.to.shared.u64 t, %1; cvt.u32.u64 %0, t; }"
        : "=r"(a) : "l"(p));
    return a;
}
__device__ __forceinline__ void cp16(uint32_t dst, const void* src) {
    asm volatile("cp.async.cg.shared.global [%0], [%1], 16;"
                 :: "r"(dst), "l"(src) : "memory");
}
#define CP_COMMIT() asm volatile("cp.async.commit_group;" ::: "memory")
#define CP_WAIT(n)  asm volatile("cp.async.wait_group %0;" :: "n"(n) : "memory")

#define LDSM4(r, addr)                                                         \
    asm volatile("ldmatrix.sync.aligned.m8n8.x4.shared.b16 "                   \
                 "{%0, %1, %2, %3}, [%4];"                                     \
                 : "=r"((r)[0]), "=r"((r)[1]), "=r"((r)[2]), "=r"((r)[3])      \
                 : "r"(addr))

#define MMA16816(c, a, b)                                                      \
    asm volatile("mma.sync.aligned.m16n8k16.row.col.f32.f16.f16.f32 "          \
                 "{%0, %1, %2, %3}, {%4, %5, %6, %7}, {%8, %9}, "              \
                 "{%0, %1, %2, %3};"                                           \
                 : "+f"((c)[0]), "+f"((c)[1]), "+f"((c)[2]), "+f"((c)[3])      \
                 : "r"((a)[0]), "r"((a)[1]), "r"((a)[2]), "r"((a)[3]),         \
                   "r"((b)[0]), "r"((b)[1]))

// ---------------------------------------------------------------------------
// conv_w: w_out -> fp16 hi/lo [n][c];  w_v -> transposed fp16 hi/lo [k][c]
// ---------------------------------------------------------------------------
__global__ __launch_bounds__(256) void conv_w_kernel(
    const float* __restrict__ w_qkv, const float* __restrict__ w_out)
{
    const int tid = threadIdx.x;
    const int b = blockIdx.x;

    if (b < 128) {
        const float4* __restrict__ w4 = reinterpret_cast<const float4*>(w_out);
        int i = b * 256 + tid;
        #pragma unroll
        for (int it = 0; it < 4; it++, i += 32768) {
            float4 v = w4[i];
            __half h0 = __float2half_rn(v.x), h1 = __float2half_rn(v.y);
            __half h2 = __float2half_rn(v.z), h3 = __float2half_rn(v.w);
            __half2* ho = reinterpret_cast<__half2*>(g_WOhi);
            __half2* lo = reinterpret_cast<__half2*>(g_WOlo);
            ho[i * 2 + 0] = __half2(h0, h1);
            ho[i * 2 + 1] = __half2(h2, h3);
            lo[i * 2 + 0] = __half2(__float2half_rn(v.x - __half2float(h0)),
                                    __float2half_rn(v.y - __half2float(h1)));
            lo[i * 2 + 1] = __half2(__float2half_rn(v.z - __half2float(h2)),
                                    __float2half_rn(v.w - __half2float(h3)));
        }
        return;
    }

    // w_v transpose: w_v[c][k] (rows [1024,1536) of w_qkv) -> WvT[k][c]
    __shared__ float tile[32][33];
    const int bb = b - 128;                  // 0..511
    const int k0 = (bb & 31) * 32;
    const int c0 = (bb >> 5) * 32;
    const int tx = tid & 31, ty = tid >> 5;
    const float* __restrict__ wv = w_qkv + (size_t)2 * HIDDEN * DIM;

    #pragma unroll
    for (int j = 0; j < 4; j++)
        tile[ty + j * 8][tx] = wv[(size_t)(c0 + ty + j * 8) * DIM + k0 + tx];
    __syncthreads();
    #pragma unroll
    for (int j = 0; j < 4; j++) {
        int k = k0 + ty + j * 8;
        float v = tile[tx][ty + j * 8];
        __half h = __float2half_rn(v);
        g_WvThi[(size_t)k * HIDDEN + c0 + tx] = h;
        g_WvTlo[(size_t)k * HIDDEN + c0 + tx] =
            __float2half_rn(v - __half2float(h));
    }
}

// ---------------------------------------------------------------------------
// Fused: blocks [0,64) = prep GEMM (3-pass fp16 split HMMA);
//        blocks [64,148) = x -> fp16 grid-stride (idle SMs).
// ---------------------------------------------------------------------------
__device__ __forceinline__ void load_stage_p(uint32_t sb, int s, int m0b,
                                             int n0b, int kc, int tid)
{
    const uint32_t st = sb + (uint32_t)s * STAGE_P;
    const char* ah = reinterpret_cast<const char*>(g_WOhi);
    const char* al = reinterpret_cast<const char*>(g_WOlo);
    const char* bh = reinterpret_cast<const char*>(g_WvThi);
    const char* bl = reinterpret_cast<const char*>(g_WvTlo);
    const size_t kb = (size_t)kc * 128;

    #pragma unroll
    for (int j = 0; j < 4; j++) {
        int i = tid + j * 256;
        int r = i >> 3, c = i & 7;
        uint32_t so = (uint32_t)r * PITCH + c * 16;
        size_t ga = (size_t)(m0b + r) * 1024 + kb + c * 16;
        size_t gb = (size_t)(n0b + r) * 1024 + kb + c * 16;
        cp16(st + PA_HI + so, ah + ga);
        cp16(st + PA_LO + so, al + ga);
        cp16(st + PB_HI + so, bh + gb);
        cp16(st + PB_LO + so, bl + gb);
    }
}

__global__ __launch_bounds__(256) void prep_fused_kernel(
    const float4* __restrict__ x4)
{
    const int tid = threadIdx.x;

    if (blockIdx.x >= 64) {
        __half2* __restrict__ xo = reinterpret_cast<__half2*>(g_Xh);
        const int total = BATCH * DIM / 4;
        const int stride = 84 * 256;
        for (int i = (blockIdx.x - 64) * 256 + tid; i < total; i += stride) {
            float4 v = x4[i];
            xo[i * 2 + 0] = __floats2half2_rn(v.x, v.y);
            xo[i * 2 + 1] = __floats2half2_rn(v.z, v.w);
        }
        return;
    }

    extern __shared__ char smem[];
    const uint32_t sb = smem_u32(smem);
    const int lane = tid & 31, wid = tid >> 5;
    const int wm = wid & 1, wn = wid >> 1;
    const int m0b = (blockIdx.x >> 3) * 128;
    const int n0b = (blockIdx.x & 7) * 128;

    float c[4][4][4] = {};

    const int rowA = lane & 15;
    const int colA = (lane >> 4) * 8;
    const int rowB = (lane & 7) + ((lane >> 4) << 3);
    const int colB = ((lane >> 3) & 1) * 8;
    const uint32_t pA = (uint32_t)(wm * 64 + rowA) * PITCH + colA * 2;
    const uint32_t pB = (uint32_t)(wn * 32 + rowB) * PITCH + colB * 2;

    load_stage_p(sb, 0, m0b, n0b, 0, tid);
    CP_COMMIT();

    for (int kc = 0; kc < KCHUNKSP; kc++) {
        const int s = kc & 1;
        if (kc + 1 < KCHUNKSP) {
            load_stage_p(sb, s ^ 1, m0b, n0b, kc + 1, tid);
            CP_COMMIT();
            CP_WAIT(1);
        } else {
            CP_WAIT(0);
        }
        __syncthreads();

        const uint32_t st = sb + (uint32_t)s * STAGE_P;
        #pragma unroll
        for (int ks = 0; ks < 4; ks++) {
            uint32_t ah[4][4], al[4][4];
            #pragma unroll
            for (int mi = 0; mi < 4; mi++) {
                uint32_t adr = st + PA_HI + pA + mi * (16 * PITCH) + ks * 32;
                LDSM4(ah[mi], adr);
                LDSM4(al[mi], adr + (PA_LO - PA_HI));
            }
            uint32_t bh[4][2], bl[4][2];
            #pragma unroll
            for (int np = 0; np < 2; np++) {
                uint32_t adr = st + PB_HI + pB + np * (16 * PITCH) + ks * 32;
                uint32_t r[4];
                LDSM4(r, adr);
                bh[np * 2][0] = r[0]; bh[np * 2][1] = r[1];
                bh[np * 2 + 1][0] = r[2]; bh[np * 2 + 1][1] = r[3];
                LDSM4(r, adr + (PB_LO - PB_HI));
                bl[np * 2][0] = r[0]; bl[np * 2][1] = r[1];
                bl[np * 2 + 1][0] = r[2]; bl[np * 2 + 1][1] = r[3];
            }
            #pragma unroll
            for (int mi = 0; mi < 4; mi++)
                #pragma unroll
                for (int ni = 0; ni < 4; ni++) {
                    MMA16816(c[mi][ni], ah[mi], bh[ni]);
                    MMA16816(c[mi][ni], ah[mi], bl[ni]);
                    MMA16816(c[mi][ni], al[mi], bh[ni]);
                }
        }
        __syncthreads();
    }

    const int mbase = m0b + wm * 64 + (lane >> 2);
    const int nbase = n0b + wn * 32 + (lane & 3) * 2;
    #pragma unroll
    for (int ni = 0; ni < 4; ni++) {
        const int n = nbase + ni * 8;
        #pragma unroll
        for (int mi = 0; mi < 4; mi++) {
            const int m = mbase + mi * 16;
            *reinterpret_cast<__half2*>(&g_Wh[(size_t)m * DIM + n]) =
                __floats2half2_rn(c[mi][ni][0], c[mi][ni][1]);
            *reinterpret_cast<__half2*>(&g_Wh[(size_t)(m + 8) * DIM + n]) =
                __floats2half2_rn(c[mi][ni][2], c[mi][ni][3]);
        }
    }
}

// ---------------------------------------------------------------------------
// Main GEMM (R7 shape): out[b][n] = 0.125 * sum_k X[b][k]*W[n][k] + b_out[n]
// BM=128 x BN=128, 256 threads, 2x4 warp grid, 3-stage cp.async, 2 CTA/SM.
// ---------------------------------------------------------------------------
__device__ __forceinline__ void load_stage(uint32_t sb, int s, int m0b, int n0b,
                                           int kc, int tid)
{
    const uint32_t st = sb + (uint32_t)s * STAGE;
    const char* xh = reinterpret_cast<const char*>(g_Xh);
    const char* wh = reinterpret_cast<const char*>(g_Wh);
    const size_t kb = (size_t)kc * 128;

    #pragma unroll
    for (int j = 0; j < 4; j++) {
        int i = tid + j * 256;
        int r = i >> 3, c = i & 7;
        uint32_t so = (uint32_t)r * PITCH + c * 16;
        cp16(st + SA + so, xh + (size_t)(m0b + r) * 2048 + kb + c * 16);
        cp16(st + SB + so, wh + (size_t)(n0b + r) * 2048 + kb + c * 16);
    }
}

__global__ __launch_bounds__(256, 2) void gemm_mma_kernel(
    const float* __restrict__ b_out, float* __restrict__ out)
{
    extern __shared__ char smem[];
    const uint32_t sb = smem_u32(smem);
    const int tid = threadIdx.x;
    const int lane = tid & 31, wid = tid >> 5;
    const int wm = wid & 1, wn = wid >> 1;
    const int m0b = blockIdx.y * BM;
    const int n0b = blockIdx.x * BN;

    float c[4][4][4] = {};

    const int rowA = lane & 15;
    const int colA = (lane >> 4) * 8;
    const int rowB = (lane & 7) + ((lane >> 4) << 3);
    const int colB = ((lane >> 3) & 1) * 8;
    const uint32_t pA = (uint32_t)(wm * 64 + rowA) * PITCH + colA * 2;
    const uint32_t pB = (uint32_t)(wn * 32 + rowB) * PITCH + colB * 2;

    load_stage(sb, 0, m0b, n0b, 0, tid);
    CP_COMMIT();
    load_stage(sb, 1, m0b, n0b, 1, tid);
    CP_COMMIT();

    int sc = 0;
    for (int kc = 0; kc < KCHUNKS; kc++) {
        CP_WAIT(1);
        __syncthreads();

        if (kc + 2 < KCHUNKS) {
            int sp = sc + 2; if (sp >= NSTAGE) sp -= NSTAGE;
            load_stage(sb, sp, m0b, n0b, kc + 2, tid);
        }
        CP_COMMIT();

        const uint32_t st = sb + (uint32_t)sc * STAGE;
        #pragma unroll
        for (int ks = 0; ks < 4; ks++) {
            uint32_t a[4][4];
            #pragma unroll
            for (int mi = 0; mi < 4; mi++)
                LDSM4(a[mi], st + SA + pA + mi * (16 * PITCH) + ks * 32);
            uint32_t b[4][2];
            #pragma unroll
            for (int np = 0; np < 2; np++) {
                uint32_t r[4];
                LDSM4(r, st + SB + pB + np * (16 * PITCH) + ks * 32);
                b[np * 2][0] = r[0]; b[np * 2][1] = r[1];
                b[np * 2 + 1][0] = r[2]; b[np * 2 + 1][1] = r[3];
            }
            #pragma unroll
            for (int mi = 0; mi < 4; mi++)
                #pragma unroll
                for (int ni = 0; ni < 4; ni++)
                    MMA16816(c[mi][ni], a[mi], b[ni]);
        }
        if (++sc >= NSTAGE) sc -= NSTAGE;
    }

    const int mbase = m0b + wm * 64 + (lane >> 2);
    const int nbase = n0b + wn * 32 + (lane & 3) * 2;
    #pragma unroll
    for (int ni = 0; ni < 4; ni++) {
        const int n = nbase + ni * 8;
        const float2 bias = *reinterpret_cast<const float2*>(&b_out[n]);
        #pragma unroll
        for (int mi = 0; mi < 4; mi++) {
            const int m = mbase + mi * 16;
            float2 v0 = { fmaf(0.125f, c[mi][ni][0], bias.x),
                          fmaf(0.125f, c[mi][ni][1], bias.y) };
            float2 v1 = { fmaf(0.125f, c[mi][ni][2], bias.x),
                          fmaf(0.125f, c[mi][ni][3], bias.y) };
            *reinterpret_cast<float2*>(&out[(size_t)m * DIM + n]) = v0;
            *reinterpret_cast<float2*>(&out[(size_t)(m + 8) * DIM + n]) = v1;
        }
    }
}

// ---------------------------------------------------------------------------
// Row L2-normalize: out = y * (32/max(||y||,eps)) * g
// ---------------------------------------------------------------------------
__global__ __launch_bounds__(256) void rmsnorm_kernel(
    const float* __restrict__ g, float* __restrict__ y)
{
    const int warp = (blockIdx.x * blockDim.x + threadIdx.x) >> 5;
    const int lane = threadIdx.x & 31;
    if (warp >= BATCH) return;
    float* __restrict__ row = y + (size_t)warp * DIM;

    float4 vals[8];
    float ss = 0.f;
    #pragma unroll
    for (int i = 0; i < 8; i++) {
        vals[i] = *reinterpret_cast<const float4*>(&row[lane * 4 + i * 128]);
        ss += vals[i].x * vals[i].x + vals[i].y * vals[i].y +
              vals[i].z * vals[i].z + vals[i].w * vals[i].w;
    }
    #pragma unroll
    for (int o = 16; o > 0; o >>= 1) ss += __shfl_xor_sync(0xFFFFFFFFu, ss, o);
    const float inv = 32.0f / fmaxf(sqrtf(ss), 1e-12f);
    #pragma unroll
    for (int i = 0; i < 8; i++) {
        int n = lane * 4 + i * 128;
        float4 gv = *reinterpret_cast<const float4*>(&g[n]);
        float4 o;
        o.x = vals[i].x * inv * gv.x;
        o.y = vals[i].y * inv * gv.y;
        o.z = vals[i].z * inv * gv.z;
        o.w = vals[i].w * inv * gv.w;
        *reinterpret_cast<float4*>(&row[n]) = o;
    }
}

// ---------------------------------------------------------------------------
extern "C" void kernel_launch(void* const* d_in, const int* in_sizes, int n_in,
                              void* d_out, int out_size)
{
    const float* x     = (const float*)d_in[0];
    const float* w_qkv = (const float*)d_in[1];
    const float* w_out = (const float*)d_in[2];
    const float* b_out = (const float*)d_in[3];
    const float* g     = (const float*)d_in[4];
    float* out = (float*)d_out;

    cudaFuncSetAttribute(gemm_mma_kernel,
                         cudaFuncAttributeMaxDynamicSharedMemorySize, GEMM_SMEM);
    cudaFuncSetAttribute(prep_fused_kernel,
                         cudaFuncAttributeMaxDynamicSharedMemorySize, PREP_SMEM);

    conv_w_kernel<<<640, 256>>>(w_qkv, w_out);
    prep_fused_kernel<<<148, 256, PREP_SMEM>>>((const float4*)x);
    gemm_mma_kernel<<<dim3(DIM / BN, BATCH / BM), 256, GEMM_SMEM>>>(b_out, out);
    rmsnorm_kernel<<<(BATCH * 32) / 256, 256>>>(g, out);
}

// round 11
// speedup vs baseline: 1.2712x; 1.1138x over previous
#include <cuda_runtime.h>
#include <cuda_fp16.h>
#include <cstdint>

// final = rmsnorm( x @ (0.125 * w_out @ w_v)^T + b_out ) * g * 32
// R10 = R7 skeleton with prep GEMM reduced to single-pass fp16 (no hi/lo):
//   conv (full chip: x->fp16, w_out->fp16, w_v->fp16 transposed)
//   -> prep GEMM (1-pass fp16 HMMA, 64 CTAs, 2/SM)
//   -> main GEMM (BM=BN=128, 256 thr, 3-stage, 2 CTA/SM)  [R7-identical]
//   -> row L2 norm.

constexpr int DIM    = 1024;
constexpr int HIDDEN = 512;
constexpr int BATCH  = 16384;

constexpr int BM = 128;
constexpr int BN = 128;
constexpr int BK = 64;
constexpr int KCHUNKS  = DIM / BK;              // 16
constexpr int KCHUNKSP = HIDDEN / BK;           // 8
constexpr int NSTAGE = 3;

constexpr uint32_t PITCH = 144;
constexpr uint32_t SA = 0;
constexpr uint32_t SB = 128 * PITCH;
constexpr uint32_t STAGE = 2 * 128 * PITCH;     // 36864
constexpr uint32_t GEMM_SMEM = NSTAGE * STAGE;  // 110592 (also prep)

// Static device scratch (allocation-free rule).
__device__ __half g_Xh[BATCH * DIM];            // x fp16
__device__ __half g_Wh[DIM * DIM];              // W = w_out @ w_v (unscaled)
__device__ __half g_WO[DIM * HIDDEN];           // w_out fp16 [n][c]
__device__ __half g_WvT[DIM * HIDDEN];          // w_v^T fp16 [k][c]

// ---------------------------------------------------------------------------
__device__ __forceinline__ uint32_t smem_u32(const void* p) {
    uint32_t a;
    asm("{ .reg .u64 t; cvta.to.shared.u64 t, %1; cvt.u32.u64 %0, t; }"
        : "=r"(a) : "l"(p));
    return a;
}
__device__ __forceinline__ void cp16(uint32_t dst, const void* src) {
    asm volatile("cp.async.cg.shared.global [%0], [%1], 16;"
                 :: "r"(dst), "l"(src) : "memory");
}
#define CP_COMMIT() asm volatile("cp.async.commit_group;" ::: "memory")
#define CP_WAIT(n)  asm volatile("cp.async.wait_group %0;" :: "n"(n) : "memory")

#define LDSM4(r, addr)                                                         \
    asm volatile("ldmatrix.sync.aligned.m8n8.x4.shared.b16 "                   \
                 "{%0, %1, %2, %3}, [%4];"                                     \
                 : "=r"((r)[0]), "=r"((r)[1]), "=r"((r)[2]), "=r"((r)[3])      \
                 : "r"(addr))

#define MMA16816(c, a, b)                                                      \
    asm volatile("mma.sync.aligned.m16n8k16.row.col.f32.f16.f16.f32 "          \
                 "{%0, %1, %2, %3}, {%4, %5, %6, %7}, {%8, %9}, "              \
                 "{%0, %1, %2, %3};"                                           \
                 : "+f"((c)[0]), "+f"((c)[1]), "+f"((c)[2]), "+f"((c)[3])      \
                 : "r"((a)[0]), "r"((a)[1]), "r"((a)[2]), "r"((a)[3]),         \
                   "r"((b)[0]), "r"((b)[1]))

// ---------------------------------------------------------------------------
// Conversion kernel (full chip, pure memory):
//   blocks [0,2048)    : x fp32 -> fp16
//   blocks [2048,2176) : w_out -> fp16 [n][c]
//   blocks [2176,2688) : w_v -> transposed fp16 [k][c]
// ---------------------------------------------------------------------------
__global__ __launch_bounds__(256) void conv_kernel(
    const float4* __restrict__ x4,
    const float* __restrict__ w_qkv, const float* __restrict__ w_out)
{
    const int tid = threadIdx.x;
    const int b = blockIdx.x;

    if (b < 2048) {
        __half2* __restrict__ xo = reinterpret_cast<__half2*>(g_Xh);
        int i = b * 256 + tid;
        #pragma unroll
        for (int it = 0; it < 8; it++, i += 524288) {
            float4 v = x4[i];
            xo[i * 2 + 0] = __floats2half2_rn(v.x, v.y);
            xo[i * 2 + 1] = __floats2half2_rn(v.z, v.w);
        }
        return;
    }

    if (b < 2176) {
        const float4* __restrict__ w4 = reinterpret_cast<const float4*>(w_out);
        __half2* __restrict__ wo = reinterpret_cast<__half2*>(g_WO);
        int i = (b - 2048) * 256 + tid;
        #pragma unroll
        for (int it = 0; it < 4; it++, i += 32768) {
            float4 v = w4[i];
            wo[i * 2 + 0] = __floats2half2_rn(v.x, v.y);
            wo[i * 2 + 1] = __floats2half2_rn(v.z, v.w);
        }
        return;
    }

    // w_v transpose: w_v[c][k] (rows [1024,1536) of w_qkv) -> WvT[k][c]
    __shared__ float tile[32][33];
    const int bb = b - 2176;                 // 0..511
    const int k0 = (bb & 31) * 32;
    const int c0 = (bb >> 5) * 32;
    const int tx = tid & 31, ty = tid >> 5;
    const float* __restrict__ wv = w_qkv + (size_t)2 * HIDDEN * DIM;

    #pragma unroll
    for (int j = 0; j < 4; j++)
        tile[ty + j * 8][tx] = wv[(size_t)(c0 + ty + j * 8) * DIM + k0 + tx];
    __syncthreads();
    #pragma unroll
    for (int j = 0; j < 4; j++) {
        int k = k0 + ty + j * 8;
        g_WvT[(size_t)k * HIDDEN + c0 + tx] =
            __float2half_rn(tile[tx][ty + j * 8]);
    }
}

// ---------------------------------------------------------------------------
// Prep GEMM (single-pass fp16): W[n][k] = sum_c w_out[n][c] * w_vT[k][c]
// Same schedule as main GEMM; K=512 (8 chunks); epilogue writes fp16 g_Wh.
// ---------------------------------------------------------------------------
__device__ __forceinline__ void load_stage_p(uint32_t sb, int s, int m0b,
                                             int n0b, int kc, int tid)
{
    const uint32_t st = sb + (uint32_t)s * STAGE;
    const char* ah = reinterpret_cast<const char*>(g_WO);
    const char* bh = reinterpret_cast<const char*>(g_WvT);
    const size_t kb = (size_t)kc * 128;

    #pragma unroll
    for (int j = 0; j < 4; j++) {
        int i = tid + j * 256;
        int r = i >> 3, c = i & 7;
        uint32_t so = (uint32_t)r * PITCH + c * 16;
        cp16(st + SA + so, ah + (size_t)(m0b + r) * 1024 + kb + c * 16);
        cp16(st + SB + so, bh + (size_t)(n0b + r) * 1024 + kb + c * 16);
    }
}

__global__ __launch_bounds__(256, 2) void prep_gemm_kernel()
{
    extern __shared__ char smem[];
    const uint32_t sb = smem_u32(smem);
    const int tid = threadIdx.x;
    const int lane = tid & 31, wid = tid >> 5;
    const int wm = wid & 1, wn = wid >> 1;
    const int m0b = blockIdx.y * BM;     // n-dim of W
    const int n0b = blockIdx.x * BN;     // k-dim of W

    float c[4][4][4] = {};

    const int rowA = lane & 15;
    const int colA = (lane >> 4) * 8;
    const int rowB = (lane & 7) + ((lane >> 4) << 3);
    const int colB = ((lane >> 3) & 1) * 8;
    const uint32_t pA = (uint32_t)(wm * 64 + rowA) * PITCH + colA * 2;
    const uint32_t pB = (uint32_t)(wn * 32 + rowB) * PITCH + colB * 2;

    load_stage_p(sb, 0, m0b, n0b, 0, tid);
    CP_COMMIT();
    load_stage_p(sb, 1, m0b, n0b, 1, tid);
    CP_COMMIT();

    int sc = 0;
    for (int kc = 0; kc < KCHUNKSP; kc++) {
        CP_WAIT(1);
        __syncthreads();

        if (kc + 2 < KCHUNKSP) {
            int sp = sc + 2; if (sp >= NSTAGE) sp -= NSTAGE;
            load_stage_p(sb, sp, m0b, n0b, kc + 2, tid);
        }
        CP_COMMIT();

        const uint32_t st = sb + (uint32_t)sc * STAGE;
        #pragma unroll
        for (int ks = 0; ks < 4; ks++) {
            uint32_t a[4][4];
            #pragma unroll
            for (int mi = 0; mi < 4; mi++)
                LDSM4(a[mi], st + SA + pA + mi * (16 * PITCH) + ks * 32);
            uint32_t b[4][2];
            #pragma unroll
            for (int np = 0; np < 2; np++) {
                uint32_t r[4];
                LDSM4(r, st + SB + pB + np * (16 * PITCH) + ks * 32);
                b[np * 2][0] = r[0]; b[np * 2][1] = r[1];
                b[np * 2 + 1][0] = r[2]; b[np * 2 + 1][1] = r[3];
            }
            #pragma unroll
            for (int mi = 0; mi < 4; mi++)
                #pragma unroll
                for (int ni = 0; ni < 4; ni++)
                    MMA16816(c[mi][ni], a[mi], b[ni]);
        }
        if (++sc >= NSTAGE) sc -= NSTAGE;
    }

    const int mbase = m0b + wm * 64 + (lane >> 2);
    const int nbase = n0b + wn * 32 + (lane & 3) * 2;
    #pragma unroll
    for (int ni = 0; ni < 4; ni++) {
        const int n = nbase + ni * 8;
        #pragma unroll
        for (int mi = 0; mi < 4; mi++) {
            const int m = mbase + mi * 16;
            *reinterpret_cast<__half2*>(&g_Wh[(size_t)m * DIM + n]) =
                __floats2half2_rn(c[mi][ni][0], c[mi][ni][1]);
            *reinterpret_cast<__half2*>(&g_Wh[(size_t)(m + 8) * DIM + n]) =
                __floats2half2_rn(c[mi][ni][2], c[mi][ni][3]);
        }
    }
}

// ---------------------------------------------------------------------------
// Main GEMM (R7-identical): out[b][n] = 0.125*sum_k X[b][k]*W[n][k] + b_out[n]
// ---------------------------------------------------------------------------
__device__ __forceinline__ void load_stage(uint32_t sb, int s, int m0b, int n0b,
                                           int kc, int tid)
{
    const uint32_t st = sb + (uint32_t)s * STAGE;
    const char* xh = reinterpret_cast<const char*>(g_Xh);
    const char* wh = reinterpret_cast<const char*>(g_Wh);
    const size_t kb = (size_t)kc * 128;

    #pragma unroll
    for (int j = 0; j < 4; j++) {
        int i = tid + j * 256;
        int r = i >> 3, c = i & 7;
        uint32_t so = (uint32_t)r * PITCH + c * 16;
        cp16(st + SA + so, xh + (size_t)(m0b + r) * 2048 + kb + c * 16);
        cp16(st + SB + so, wh + (size_t)(n0b + r) * 2048 + kb + c * 16);
    }
}

__global__ __launch_bounds__(256, 2) void gemm_mma_kernel(
    const float* __restrict__ b_out, float* __restrict__ out)
{
    extern __shared__ char smem[];
    const uint32_t sb = smem_u32(smem);
    const int tid = threadIdx.x;
    const int lane = tid & 31, wid = tid >> 5;
    const int wm = wid & 1, wn = wid >> 1;
    const int m0b = blockIdx.y * BM;
    const int n0b = blockIdx.x * BN;

    float c[4][4][4] = {};

    const int rowA = lane & 15;
    const int colA = (lane >> 4) * 8;
    const int rowB = (lane & 7) + ((lane >> 4) << 3);
    const int colB = ((lane >> 3) & 1) * 8;
    const uint32_t pA = (uint32_t)(wm * 64 + rowA) * PITCH + colA * 2;
    const uint32_t pB = (uint32_t)(wn * 32 + rowB) * PITCH + colB * 2;

    load_stage(sb, 0, m0b, n0b, 0, tid);
    CP_COMMIT();
    load_stage(sb, 1, m0b, n0b, 1, tid);
    CP_COMMIT();

    int sc = 0;
    for (int kc = 0; kc < KCHUNKS; kc++) {
        CP_WAIT(1);
        __syncthreads();

        if (kc + 2 < KCHUNKS) {
            int sp = sc + 2; if (sp >= NSTAGE) sp -= NSTAGE;
            load_stage(sb, sp, m0b, n0b, kc + 2, tid);
        }
        CP_COMMIT();

        const uint32_t st = sb + (uint32_t)sc * STAGE;
        #pragma unroll
        for (int ks = 0; ks < 4; ks++) {
            uint32_t a[4][4];
            #pragma unroll
            for (int mi = 0; mi < 4; mi++)
                LDSM4(a[mi], st + SA + pA + mi * (16 * PITCH) + ks * 32);
            uint32_t b[4][2];
            #pragma unroll
            for (int np = 0; np < 2; np++) {
                uint32_t r[4];
                LDSM4(r, st + SB + pB + np * (16 * PITCH) + ks * 32);
                b[np * 2][0] = r[0]; b[np * 2][1] = r[1];
                b[np * 2 + 1][0] = r[2]; b[np * 2 + 1][1] = r[3];
            }
            #pragma unroll
            for (int mi = 0; mi < 4; mi++)
                #pragma unroll
                for (int ni = 0; ni < 4; ni++)
                    MMA16816(c[mi][ni], a[mi], b[ni]);
        }
        if (++sc >= NSTAGE) sc -= NSTAGE;
    }

    const int mbase = m0b + wm * 64 + (lane >> 2);
    const int nbase = n0b + wn * 32 + (lane & 3) * 2;
    #pragma unroll
    for (int ni = 0; ni < 4; ni++) {
        const int n = nbase + ni * 8;
        const float2 bias = *reinterpret_cast<const float2*>(&b_out[n]);
        #pragma unroll
        for (int mi = 0; mi < 4; mi++) {
            const int m = mbase + mi * 16;
            float2 v0 = { fmaf(0.125f, c[mi][ni][0], bias.x),
                          fmaf(0.125f, c[mi][ni][1], bias.y) };
            float2 v1 = { fmaf(0.125f, c[mi][ni][2], bias.x),
                          fmaf(0.125f, c[mi][ni][3], bias.y) };
            *reinterpret_cast<float2*>(&out[(size_t)m * DIM + n]) = v0;
            *reinterpret_cast<float2*>(&out[(size_t)(m + 8) * DIM + n]) = v1;
        }
    }
}

// ---------------------------------------------------------------------------
// Row L2-normalize: out = y * (32/max(||y||,eps)) * g
// ---------------------------------------------------------------------------
__global__ __launch_bounds__(256) void rmsnorm_kernel(
    const float* __restrict__ g, float* __restrict__ y)
{
    const int warp = (blockIdx.x * blockDim.x + threadIdx.x) >> 5;
    const int lane = threadIdx.x & 31;
    if (warp >= BATCH) return;
    float* __restrict__ row = y + (size_t)warp * DIM;

    float4 vals[8];
    float ss = 0.f;
    #pragma unroll
    for (int i = 0; i < 8; i++) {
        vals[i] = *reinterpret_cast<const float4*>(&row[lane * 4 + i * 128]);
        ss += vals[i].x * vals[i].x + vals[i].y * vals[i].y +
              vals[i].z * vals[i].z + vals[i].w * vals[i].w;
    }
    #pragma unroll
    for (int o = 16; o > 0; o >>= 1) ss += __shfl_xor_sync(0xFFFFFFFFu, ss, o);
    const float inv = 32.0f / fmaxf(sqrtf(ss), 1e-12f);
    #pragma unroll
    for (int i = 0; i < 8; i++) {
        int n = lane * 4 + i * 128;
        float4 gv = *reinterpret_cast<const float4*>(&g[n]);
        float4 o;
        o.x = vals[i].x * inv * gv.x;
        o.y = vals[i].y * inv * gv.y;
        o.z = vals[i].z * inv * gv.z;
        o.w = vals[i].w * inv * gv.w;
        *reinterpret_cast<float4*>(&row[n]) = o;
    }
}

// ---------------------------------------------------------------------------
extern "C" void kernel_launch(void* const* d_in, const int* in_sizes, int n_in,
                              void* d_out, int out_size)
{
    const float* x     = (const float*)d_in[0];
    const float* w_qkv = (const float*)d_in[1];
    const float* w_out = (const float*)d_in[2];
    const float* b_out = (const float*)d_in[3];
    const float* g     = (const float*)d_in[4];
    float* out = (float*)d_out;

    cudaFuncSetAttribute(gemm_mma_kernel,
                         cudaFuncAttributeMaxDynamicSharedMemorySize, GEMM_SMEM);
    cudaFuncSetAttribute(prep_gemm_kernel,
                         cudaFuncAttributeMaxDynamicSharedMemorySize, GEMM_SMEM);

    conv_kernel<<<2688, 256>>>((const float4*)x, w_qkv, w_out);
    prep_gemm_kernel<<<dim3(DIM / BN, DIM / BM), 256, GEMM_SMEM>>>();
    gemm_mma_kernel<<<dim3(DIM / BN, BATCH / BM), 256, GEMM_SMEM>>>(b_out, out);
    rmsnorm_kernel<<<(BATCH * 32) / 256, 256>>>(g, out);
}